// round 2
// baseline (speedup 1.0000x reference)
#include <cuda_runtime.h>
#include <cuda_bf16.h>

#define NN 16
#define VV 5023
#define FF 9976
#define HH 512
#define WW 512
#define NV (NN * VV)            // 80368
#define NPIX (NN * HH * WW)     // 4194304

__device__ unsigned int g_min_bits;
__device__ unsigned int g_max_bits;
__device__ float g_znorm[NV];

// Monotonic encoding of float -> uint so atomicMin/Max give float min/max.
__device__ __forceinline__ unsigned int enc_f(float f) {
    unsigned int u = __float_as_uint(f);
    return (u & 0x80000000u) ? ~u : (u | 0x80000000u);
}
__device__ __forceinline__ float dec_f(unsigned int s) {
    return __uint_as_float((s & 0x80000000u) ? (s ^ 0x80000000u) : ~s);
}

__global__ void init_minmax_kernel() {
    g_min_bits = 0xFFFFFFFFu;
    g_max_bits = 0u;
}

// Reduce min/max of tv[:, :, 2] (stride-3 gather, 80368 elements).
__global__ void minmax_kernel(const float* __restrict__ tv) {
    int i = blockIdx.x * blockDim.x + threadIdx.x;
    float z = (i < NV) ? tv[3 * i + 2] : tv[2];  // pad with a real value
    // warp reduce
    float mn = z, mx = z;
    #pragma unroll
    for (int o = 16; o > 0; o >>= 1) {
        mn = fminf(mn, __shfl_xor_sync(0xFFFFFFFFu, mn, o));
        mx = fmaxf(mx, __shfl_xor_sync(0xFFFFFFFFu, mx, o));
    }
    __shared__ float smn[8], smx[8];
    int lane = threadIdx.x & 31, w = threadIdx.x >> 5;
    if (lane == 0) { smn[w] = mn; smx[w] = mx; }
    __syncthreads();
    if (threadIdx.x == 0) {
        float bmn = smn[0], bmx = smx[0];
        int nw = (blockDim.x + 31) >> 5;
        for (int k = 1; k < nw; k++) {
            bmn = fminf(bmn, smn[k]);
            bmx = fmaxf(bmx, smx[k]);
        }
        atomicMin(&g_min_bits, enc_f(bmn));
        atomicMax(&g_max_bits, enc_f(bmx));
    }
}

// znorm[n*V+v] = (R - fl(z - m)) / R  with R = fl(M - m)  (matches reference rounding)
__global__ void znorm_kernel(const float* __restrict__ tv) {
    int i = blockIdx.x * blockDim.x + threadIdx.x;
    if (i >= NV) return;
    float m = dec_f(g_min_bits);
    float M = dec_f(g_max_bits);
    float R = M - m;
    float z = tv[3 * i + 2];
    g_znorm[i] = (R - (z - m)) / R;
}

// Per-pixel interpolation. 4 pixels per thread, vectorized streaming I/O,
// branch-free gathers (predicated result) so all LDGs issue -> high MLP.
__global__ void __launch_bounds__(256) pixel_kernel(
    const float* __restrict__ bary,
    const int* __restrict__ faces,
    const int* __restrict__ p2f,
    float* __restrict__ out)
{
    int t = blockIdx.x * blockDim.x + threadIdx.x;
    int base = t * 4;
    if (base >= NPIX) return;

    int4 pv = *reinterpret_cast<const int4*>(p2f + base);
    const float4 b0 = *reinterpret_cast<const float4*>(bary + (long long)base * 3);
    const float4 b1 = *reinterpret_cast<const float4*>(bary + (long long)base * 3 + 4);
    const float4 b2 = *reinterpret_cast<const float4*>(bary + (long long)base * 3 + 8);

    float bw[4][3] = {
        {b0.x, b0.y, b0.z},
        {b0.w, b1.x, b1.y},
        {b1.z, b1.w, b2.x},
        {b2.y, b2.z, b2.w}
    };
    int ps[4] = {pv.x, pv.y, pv.z, pv.w};
    float res[4];

    #pragma unroll
    for (int i = 0; i < 4; i++) {
        int p = ps[i];
        bool valid = (p >= 0);
        int pc = valid ? p : 0;
        int img = pc / FF;             // compile-time magic-mul
        int f = pc - img * FF;
        int v0 = __ldg(faces + 3 * f);
        int v1 = __ldg(faces + 3 * f + 1);
        int v2 = __ldg(faces + 3 * f + 2);
        int ofs = img * VV;
        float s = bw[i][0] * g_znorm[ofs + v0]
                + bw[i][1] * g_znorm[ofs + v1]
                + bw[i][2] * g_znorm[ofs + v2];
        res[i] = valid ? s : 0.0f;
    }

    *reinterpret_cast<float4*>(out + base) = make_float4(res[0], res[1], res[2], res[3]);
}

extern "C" void kernel_launch(void* const* d_in, const int* in_sizes, int n_in,
                              void* d_out, int out_size) {
    // Identify inputs by element count (robust to ordering).
    const float* tv = nullptr;      // 241104
    const float* bary = nullptr;    // 12582912
    const int* faces = nullptr;     // 29928
    const int* p2f = nullptr;       // 4194304
    for (int i = 0; i < n_in; i++) {
        switch (in_sizes[i]) {
            case NN * VV * 3:            tv    = (const float*)d_in[i]; break;
            case NN * HH * WW * 3:       bary  = (const float*)d_in[i]; break;
            case FF * 3:                 faces = (const int*)d_in[i];   break;
            case NN * HH * WW:           p2f   = (const int*)d_in[i];   break;
        }
    }
    float* out = (float*)d_out;

    init_minmax_kernel<<<1, 1>>>();
    minmax_kernel<<<(NV + 255) / 256, 256>>>(tv);
    znorm_kernel<<<(NV + 255) / 256, 256>>>(tv);
    pixel_kernel<<<(NPIX / 4 + 255) / 256, 256>>>(bary, faces, p2f, out);
}

// round 3
// speedup vs baseline: 1.8042x; 1.8042x over previous
#include <cuda_runtime.h>
#include <cuda_bf16.h>

#define NN 16
#define VV 5023
#define FF 9976
#define HH 512
#define WW 512
#define NV (NN * VV)            // 80368
#define NF (NN * FF)            // 159616
#define NPIX (NN * HH * WW)     // 4194304

__device__ unsigned int g_min_bits;
__device__ unsigned int g_max_bits;
__device__ float4 g_fz[NF];     // per-(image,face) vertex z-norms, padded to 16B

// Monotonic encoding of float -> uint so atomicMin/Max give float min/max.
__device__ __forceinline__ unsigned int enc_f(float f) {
    unsigned int u = __float_as_uint(f);
    return (u & 0x80000000u) ? ~u : (u | 0x80000000u);
}
__device__ __forceinline__ float dec_f(unsigned int s) {
    return __uint_as_float((s & 0x80000000u) ? (s ^ 0x80000000u) : ~s);
}

__global__ void init_minmax_kernel() {
    g_min_bits = 0xFFFFFFFFu;
    g_max_bits = 0u;
}

// Reduce min/max of tv[:, :, 2] (stride-3, 80368 elements).
__global__ void minmax_kernel(const float* __restrict__ tv) {
    int i = blockIdx.x * blockDim.x + threadIdx.x;
    float z = (i < NV) ? tv[3 * i + 2] : tv[2];  // pad with a real value
    float mn = z, mx = z;
    #pragma unroll
    for (int o = 16; o > 0; o >>= 1) {
        mn = fminf(mn, __shfl_xor_sync(0xFFFFFFFFu, mn, o));
        mx = fmaxf(mx, __shfl_xor_sync(0xFFFFFFFFu, mx, o));
    }
    __shared__ float smn[8], smx[8];
    int lane = threadIdx.x & 31, w = threadIdx.x >> 5;
    if (lane == 0) { smn[w] = mn; smx[w] = mx; }
    __syncthreads();
    if (threadIdx.x == 0) {
        float bmn = smn[0], bmx = smx[0];
        int nw = (blockDim.x + 31) >> 5;
        for (int k = 1; k < nw; k++) {
            bmn = fminf(bmn, smn[k]);
            bmx = fmaxf(bmx, smx[k]);
        }
        atomicMin(&g_min_bits, enc_f(bmn));
        atomicMax(&g_max_bits, enc_f(bmx));
    }
}

// Build per-(image,face) table: fz[n*F+f].{x,y,z} = (R - fl(z_vc - m)) / R
// Matches reference rounding: z' = fl(z - m); z'' = z' / fl(M - m)... applied as
// (R - z')/R with R = fl(M-m).
__global__ void facez_kernel(const float* __restrict__ tv,
                             const int* __restrict__ faces) {
    int t = blockIdx.x * blockDim.x + threadIdx.x;
    if (t >= NF) return;
    int n = t / FF;                // compile-time magic-mul
    int f = t - n * FF;
    float m = dec_f(g_min_bits);
    float M = dec_f(g_max_bits);
    float R = M - m;
    float invR = 1.0f;             // keep exact division for rounding parity
    (void)invR;
    int v0 = __ldg(faces + 3 * f);
    int v1 = __ldg(faces + 3 * f + 1);
    int v2 = __ldg(faces + 3 * f + 2);
    long long vb = (long long)n * VV;
    float z0 = tv[3 * (vb + v0) + 2];
    float z1 = tv[3 * (vb + v1) + 2];
    float z2 = tv[3 * (vb + v2) + 2];
    float4 r;
    r.x = (R - (z0 - m)) / R;
    r.y = (R - (z1 - m)) / R;
    r.z = (R - (z2 - m)) / R;
    r.w = 0.0f;
    g_fz[t] = r;
}

// Per-pixel interpolation. 4 pixels/thread, vectorized streaming I/O; the only
// scattered access is ONE aligned float4 gather per pixel into the 2.55MB
// L2-resident fz table. Branch-free so all gathers issue -> high MLP.
__global__ void __launch_bounds__(256) pixel_kernel(
    const float* __restrict__ bary,
    const int* __restrict__ p2f,
    float* __restrict__ out)
{
    int t = blockIdx.x * blockDim.x + threadIdx.x;
    int base = t * 4;
    if (base >= NPIX) return;

    int4 pv = *reinterpret_cast<const int4*>(p2f + base);
    const float4 b0 = *reinterpret_cast<const float4*>(bary + (long long)base * 3);
    const float4 b1 = *reinterpret_cast<const float4*>(bary + (long long)base * 3 + 4);
    const float4 b2 = *reinterpret_cast<const float4*>(bary + (long long)base * 3 + 8);

    float bw[4][3] = {
        {b0.x, b0.y, b0.z},
        {b0.w, b1.x, b1.y},
        {b1.z, b1.w, b2.x},
        {b2.y, b2.z, b2.w}
    };
    int ps[4] = {pv.x, pv.y, pv.z, pv.w};
    float res[4];

    #pragma unroll
    for (int i = 0; i < 4; i++) {
        int p = ps[i];
        bool valid = (p >= 0);
        int pc = valid ? p : 0;
        float4 z = g_fz[pc];
        float s = bw[i][0] * z.x + bw[i][1] * z.y + bw[i][2] * z.z;
        res[i] = valid ? s : 0.0f;
    }

    *reinterpret_cast<float4*>(out + base) = make_float4(res[0], res[1], res[2], res[3]);
}

extern "C" void kernel_launch(void* const* d_in, const int* in_sizes, int n_in,
                              void* d_out, int out_size) {
    const float* tv = nullptr;      // 241104
    const float* bary = nullptr;    // 12582912
    const int* faces = nullptr;     // 29928
    const int* p2f = nullptr;       // 4194304
    for (int i = 0; i < n_in; i++) {
        switch (in_sizes[i]) {
            case NN * VV * 3:            tv    = (const float*)d_in[i]; break;
            case NN * HH * WW * 3:       bary  = (const float*)d_in[i]; break;
            case FF * 3:                 faces = (const int*)d_in[i];   break;
            case NN * HH * WW:           p2f   = (const int*)d_in[i];   break;
        }
    }
    float* out = (float*)d_out;

    init_minmax_kernel<<<1, 1>>>();
    minmax_kernel<<<(NV + 255) / 256, 256>>>(tv);
    facez_kernel<<<(NF + 255) / 256, 256>>>(tv, faces);
    pixel_kernel<<<(NPIX / 4 + 255) / 256, 256>>>(bary, p2f, out);
}